// round 1
// baseline (speedup 1.0000x reference)
#include <cuda_runtime.h>
#include <cstdint>
#include <cstddef>

#define B_ROWS 32768
#define DDIM   128
#define HDIM   64
#define NSTEPS 32
#define TILE_R 64
#define CTA_THREADS 256
#define SROW   68   // padded row stride (floats): even (8B-aligned pairs), 272B rows

// Pre-transposed / gate-packed weight scratch (allowed: __device__ globals)
__device__ float4 g_W0p[192 * 64];   // [k][unit] -> (Wi,Wf,Wg,Wo), k: 0..127 = y-input, 128..191 = h0
__device__ float4 g_W1p[128 * 64];   // [k][unit], k: 0..63 = h0-input, 64..127 = h1
__device__ float  g_WfcT[64 * 128];  // [k][d]

// ---------- packed f32x2 helpers ----------
static __device__ __forceinline__ unsigned long long pack2(float lo, float hi) {
    unsigned long long r;
    asm("mov.b64 %0, {%1, %2};" : "=l"(r) : "f"(lo), "f"(hi));
    return r;
}
static __device__ __forceinline__ void unpack2(unsigned long long v, float& lo, float& hi) {
    asm("mov.b64 {%0, %1}, %2;" : "=f"(lo), "=f"(hi) : "l"(v));
}
static __device__ __forceinline__ unsigned long long ffma2(unsigned long long a,
                                                           unsigned long long b,
                                                           unsigned long long c) {
    unsigned long long d;
    asm("fma.rn.f32x2 %0, %1, %2, %3;" : "=l"(d) : "l"(a), "l"(b), "l"(c));
    return d;
}

static __device__ __forceinline__ float sigm(float x) {
    return __fdividef(1.0f, 1.0f + __expf(-x));
}
static __device__ __forceinline__ float tanh_fast(float x) {
    float e = __expf(-2.0f * fabsf(x));
    float t = __fdividef(1.0f - e, 1.0f + e);
    return copysignf(t, x);
}

// ---------- weight prep: transpose + gate-pack ----------
__global__ void prep_kernel(const float* __restrict__ Wih0, const float* __restrict__ Whh0,
                            const float* __restrict__ Wih1, const float* __restrict__ Whh1,
                            const float* __restrict__ Wfc) {
    int i = blockIdx.x * blockDim.x + threadIdx.x;
    int stride = gridDim.x * blockDim.x;

    for (int idx = i; idx < 192 * 64; idx += stride) {
        int k = idx >> 6, u = idx & 63;
        float4 v;
        if (k < 128) {
            v.x = Wih0[(u      ) * 128 + k];
            v.y = Wih0[(u +  64) * 128 + k];
            v.z = Wih0[(u + 128) * 128 + k];
            v.w = Wih0[(u + 192) * 128 + k];
        } else {
            int kk = k - 128;
            v.x = Whh0[(u      ) * 64 + kk];
            v.y = Whh0[(u +  64) * 64 + kk];
            v.z = Whh0[(u + 128) * 64 + kk];
            v.w = Whh0[(u + 192) * 64 + kk];
        }
        g_W0p[idx] = v;
    }
    for (int idx = i; idx < 128 * 64; idx += stride) {
        int k = idx >> 6, u = idx & 63;
        float4 v;
        if (k < 64) {
            v.x = Wih1[(u      ) * 64 + k];
            v.y = Wih1[(u +  64) * 64 + k];
            v.z = Wih1[(u + 128) * 64 + k];
            v.w = Wih1[(u + 192) * 64 + k];
        } else {
            int kk = k - 64;
            v.x = Whh1[(u      ) * 64 + kk];
            v.y = Whh1[(u +  64) * 64 + kk];
            v.z = Whh1[(u + 128) * 64 + kk];
            v.w = Whh1[(u + 192) * 64 + kk];
        }
        g_W1p[idx] = v;
    }
    for (int idx = i; idx < 64 * 128; idx += stride) {
        int k = idx >> 7, d = idx & 127;
        g_WfcT[idx] = Wfc[d * 64 + k];
    }
}

// Accumulate 4 gates over nK features from state array s_base (k-major, stride SROW),
// weights from Wp starting at k-row kw0. Rows are the 8 f32x2 pairs at r0.
static __device__ __forceinline__ void gate_accum(
    const float4* __restrict__ Wp, int kw0, int nK, int u,
    const float* __restrict__ s_base, int r0,
    unsigned long long* ai, unsigned long long* af,
    unsigned long long* ag, unsigned long long* ao) {
#pragma unroll 4
    for (int k = 0; k < nK; ++k) {
        float4 wv = Wp[(kw0 + k) * 64 + u];
        unsigned long long wi = pack2(wv.x, wv.x);
        unsigned long long wf = pack2(wv.y, wv.y);
        unsigned long long wg = pack2(wv.z, wv.z);
        unsigned long long wo = pack2(wv.w, wv.w);
        const unsigned long long* s =
            reinterpret_cast<const unsigned long long*>(s_base + k * SROW + r0);
#pragma unroll
        for (int p = 0; p < 8; ++p) {
            unsigned long long sv = s[p];
            ai[p] = ffma2(wi, sv, ai[p]);
            af[p] = ffma2(wf, sv, af[p]);
            ag[p] = ffma2(wg, sv, ag[p]);
            ao[p] = ffma2(wo, sv, ao[p]);
        }
    }
}

extern __shared__ float smem[];

__global__ __launch_bounds__(CTA_THREADS, 1)
void lstm_kernel(const float* __restrict__ x,
                 const float* __restrict__ b0, const float* __restrict__ b1,
                 const float* __restrict__ bfc,
                 float* __restrict__ ystack, float* __restrict__ ylast) {
    float* y_sm  = smem;                      // [128][SROW]
    float* h0_sm = y_sm  + DDIM * SROW;       // [64][SROW]
    float* h1_sm = h0_sm + HDIM * SROW;       // [64][SROW]

    const int tid  = threadIdx.x;
    const int lane = tid & 31;
    const int w    = tid >> 5;
    const int row0 = blockIdx.x * TILE_R;

    // Load x tile into y_sm (k-major), zero h states
    for (int i = tid; i < TILE_R * DDIM; i += CTA_THREADS) {
        int r = i >> 7, d = i & 127;
        y_sm[d * SROW + r] = x[(size_t)(row0 + r) * DDIM + d];
    }
    for (int i = tid; i < HDIM * SROW; i += CTA_THREADS) {
        h0_sm[i] = 0.0f;
        h1_sm[i] = 0.0f;
    }

    // LSTM gate role: lane -> unit, rows register-blocked 16/warp
    const int ublk   = w & 1;
    const int rowblk = w >> 1;          // 0..3
    const int u      = ublk * 32 + lane;
    const int r0     = rowblk * 16;

    // FC role: lane -> output dim, 32 rows/warp
    const int dblk    = w & 3;
    const int rowblkF = w >> 2;         // 0..1
    const int d_fc    = dblk * 32 + lane;
    const int rF0     = rowblkF * 32;

    float c0[16], c1[16];
#pragma unroll
    for (int i = 0; i < 16; ++i) { c0[i] = 0.0f; c1[i] = 0.0f; }

    const float bi0 = b0[u], bf0 = b0[64 + u], bg0 = b0[128 + u], bo0 = b0[192 + u];
    const float bi1 = b1[u], bf1 = b1[64 + u], bg1 = b1[128 + u], bo1 = b1[192 + u];
    const float bfc_r = bfc[d_fc];

    for (int t = 0; t < NSTEPS; ++t) {
        __syncthreads();  // states (y, h0, h1) ready

        // ---------------- layer 0 gates ----------------
        unsigned long long ai[8], af[8], ag[8], ao[8];
#pragma unroll
        for (int p = 0; p < 8; ++p) {
            ai[p] = pack2(bi0, bi0); af[p] = pack2(bf0, bf0);
            ag[p] = pack2(bg0, bg0); ao[p] = pack2(bo0, bo0);
        }
        gate_accum(g_W0p,   0, DDIM, u, y_sm,  r0, ai, af, ag, ao);
        gate_accum(g_W0p, 128, HDIM, u, h0_sm, r0, ai, af, ag, ao);

        __syncthreads();  // everyone done reading old h0

#pragma unroll
        for (int p = 0; p < 8; ++p) {
            float iv0, iv1, fv0, fv1, gv0, gv1, ov0, ov1;
            unpack2(ai[p], iv0, iv1);
            unpack2(af[p], fv0, fv1);
            unpack2(ag[p], gv0, gv1);
            unpack2(ao[p], ov0, ov1);
            float c;
            c = sigm(fv0) * c0[2 * p]     + sigm(iv0) * tanh_fast(gv0);
            c0[2 * p] = c;
            h0_sm[u * SROW + r0 + 2 * p]     = sigm(ov0) * tanh_fast(c);
            c = sigm(fv1) * c0[2 * p + 1] + sigm(iv1) * tanh_fast(gv1);
            c0[2 * p + 1] = c;
            h0_sm[u * SROW + r0 + 2 * p + 1] = sigm(ov1) * tanh_fast(c);
        }

        __syncthreads();  // new h0 visible

        // ---------------- layer 1 gates ----------------
#pragma unroll
        for (int p = 0; p < 8; ++p) {
            ai[p] = pack2(bi1, bi1); af[p] = pack2(bf1, bf1);
            ag[p] = pack2(bg1, bg1); ao[p] = pack2(bo1, bo1);
        }
        gate_accum(g_W1p,  0, HDIM, u, h0_sm, r0, ai, af, ag, ao);
        gate_accum(g_W1p, 64, HDIM, u, h1_sm, r0, ai, af, ag, ao);

        __syncthreads();  // everyone done reading old h1

#pragma unroll
        for (int p = 0; p < 8; ++p) {
            float iv0, iv1, fv0, fv1, gv0, gv1, ov0, ov1;
            unpack2(ai[p], iv0, iv1);
            unpack2(af[p], fv0, fv1);
            unpack2(ag[p], gv0, gv1);
            unpack2(ao[p], ov0, ov1);
            float c;
            c = sigm(fv0) * c1[2 * p]     + sigm(iv0) * tanh_fast(gv0);
            c1[2 * p] = c;
            h1_sm[u * SROW + r0 + 2 * p]     = sigm(ov0) * tanh_fast(c);
            c = sigm(fv1) * c1[2 * p + 1] + sigm(iv1) * tanh_fast(gv1);
            c1[2 * p + 1] = c;
            h1_sm[u * SROW + r0 + 2 * p + 1] = sigm(ov1) * tanh_fast(c);
        }

        __syncthreads();  // new h1 visible

        // ---------------- FC projection: y = Wfc @ h1 + bfc ----------------
        unsigned long long ay[16];
#pragma unroll
        for (int p = 0; p < 16; ++p) ay[p] = pack2(bfc_r, bfc_r);
#pragma unroll 4
        for (int k = 0; k < HDIM; ++k) {
            float wv = g_WfcT[k * 128 + d_fc];
            unsigned long long wp = pack2(wv, wv);
            const unsigned long long* s =
                reinterpret_cast<const unsigned long long*>(h1_sm + k * SROW + rF0);
#pragma unroll
            for (int p = 0; p < 16; ++p) ay[p] = ffma2(wp, s[p], ay[p]);
        }

        const size_t tbase = (size_t)t * B_ROWS * DDIM;
#pragma unroll
        for (int p = 0; p < 16; ++p) {
            float ylo, yhi;
            unpack2(ay[p], ylo, yhi);
            const int r = rF0 + 2 * p;
            y_sm[d_fc * SROW + r]     = ylo;
            y_sm[d_fc * SROW + r + 1] = yhi;
            if (ystack) {
                ystack[tbase + (size_t)(row0 + r)     * DDIM + d_fc] = ylo;
                ystack[tbase + (size_t)(row0 + r + 1) * DDIM + d_fc] = yhi;
            }
            if (t == NSTEPS - 1 && ylast) {
                ylast[(size_t)(row0 + r)     * DDIM + d_fc] = ylo;
                ylast[(size_t)(row0 + r + 1) * DDIM + d_fc] = yhi;
            }
        }
        // next-iteration top sync guards y_sm reads
    }
}

extern "C" void kernel_launch(void* const* d_in, const int* in_sizes, int n_in,
                              void* d_out, int out_size) {
    const float* x    = (const float*)d_in[0];
    const float* Wih0 = (const float*)d_in[1];
    const float* Whh0 = (const float*)d_in[2];
    const float* b0   = (const float*)d_in[3];
    const float* Wih1 = (const float*)d_in[4];
    const float* Whh1 = (const float*)d_in[5];
    const float* b1   = (const float*)d_in[6];
    const float* Wfc  = (const float*)d_in[7];
    const float* bfc  = (const float*)d_in[8];
    (void)in_sizes; (void)n_in;

    float* out = (float*)d_out;
    const long long BD = (long long)B_ROWS * DDIM;

    float* ylast  = nullptr;
    float* ystack = nullptr;
    if ((long long)out_size >= BD * (NSTEPS + 1)) {        // [y_last, y_stack]
        ylast  = out;
        ystack = out + BD;
    } else if ((long long)out_size >= BD * NSTEPS) {       // y_stack only
        ystack = out;
    } else {                                               // y_last only
        ylast = out;
    }

    const int smem_bytes = (DDIM + HDIM + HDIM) * SROW * sizeof(float);  // 69632
    cudaFuncSetAttribute(lstm_kernel, cudaFuncAttributeMaxDynamicSharedMemorySize, smem_bytes);

    prep_kernel<<<64, 256>>>(Wih0, Whh0, Wih1, Whh1, Wfc);
    lstm_kernel<<<B_ROWS / TILE_R, CTA_THREADS, smem_bytes>>>(x, b0, b1, bfc, ystack, ylast);
}